// round 8
// baseline (speedup 1.0000x reference)
#include <cuda_runtime.h>
#include <cuda_fp16.h>

// Problem constants (fixed by the dataset)
#define L_WIN   10
#define D_EMB   100
#define V_POI   1000
#define V_HOUR  24
#define V_WD    7
#define N_HW    (V_HOUR * V_WD)           // 168 hour*weekday combo rows
#define NROWS   (V_POI + N_HW)            // 1168 token rows (poi | hw-combo)
#define NTILES  16                        // 16 column tiles x 64 cols = 1024
#define TCOLS   64
#define NCHUNK  9                         // 16*9 = 144 blocks <= SM count

// Column-tiled token-logit table (fp16): g_TLt[tile][row][64 cols].
// One tile slice = 1168*128B = 149.5KB -> fits in one SM's L1.
//  rows [0,1000):    emb_poi[p]  . W(n)[0:100]
//  rows [1000,1168): emb_hour[h] . W(n)[100:200] + emb_wd[w] . W(n)[200:300]
// virtual cols: [0,1000)=poi logits, [1000,1024)=hour logits.
__device__ __align__(128) __half g_TLt[NTILES * NROWS * TCOLS];   // 2.39 MB

// Compact weekday-logit table (fp32): cols [0,7) weekday logits, col 7 pad.
__device__ __align__(128) float g_TLwd[NROWS * 8];                // 37 KB

// Precomputed per-sample row offsets (bytes into a tile slice) + meta.
// layout per sample (stride 24 ints): [0..19]=row*128, [20]=T=2e, [21]=inv bits.
__device__ int g_off[65536 * 24];                                 // 6.3 MB

// ---------------------------------------------------------------------------
__device__ __forceinline__ float wload(const float* __restrict__ W_poi,
                                       const float* __restrict__ W_hour,
                                       const float* __restrict__ W_wd,
                                       int n, int so, int d) {
    if (n < V_POI)          return W_poi[n * 300 + so + d];
    if (n < V_POI + V_HOUR) return W_hour[(n - V_POI) * 300 + so + d];
    if (n < 1031)           return W_wd[(n - 1024) * 300 + so + d];
    return 0.f;
}

__device__ __forceinline__ void store_tl(int r, int n, float v) {
    if (n < 1024)
        g_TLt[((n >> 6) * NROWS + r) * TCOLS + (n & 63)] = __float2half_rn(v);
    else if (n < 1032)
        g_TLwd[r * 8 + (n - 1024)] = v;
}

// ---------------------------------------------------------------------------
// Build kernel A: poi rows (K=100). Tile 16 rows x 64 cols, 2x2 per thread.
// ---------------------------------------------------------------------------
__global__ void build_poi_kernel(const float* __restrict__ emb_poi,
                                 const float* __restrict__ W_poi,
                                 const float* __restrict__ W_hour,
                                 const float* __restrict__ W_wd) {
    __shared__ float Wst[100][65];
    __shared__ float Es[16][100];

    const int n0  = blockIdx.x * 64;
    const int r0  = blockIdx.y * 16;
    const int tid = threadIdx.y * 32 + threadIdx.x;

    for (int idx = tid; idx < 64 * 100; idx += 256) {
        int c = idx / 100, d = idx - c * 100;
        Wst[d][c] = wload(W_poi, W_hour, W_wd, n0 + c, 0, d);
    }
    for (int idx = tid; idx < 16 * 100; idx += 256) {
        int i = idx / 100, d = idx - i * 100;
        int r = r0 + i;
        Es[i][d] = (r < V_POI) ? emb_poi[r * D_EMB + d] : 0.f;
    }
    __syncthreads();

    const int j  = threadIdx.x;
    const int i0 = threadIdx.y;
    const int i1 = threadIdx.y + 8;

    float a00 = 0.f, a01 = 0.f, a10 = 0.f, a11 = 0.f;
#pragma unroll 10
    for (int d = 0; d < 100; d++) {
        float w0 = Wst[d][j], w1 = Wst[d][j + 32];
        float e0 = Es[i0][d], e1 = Es[i1][d];
        a00 += e0 * w0; a01 += e0 * w1;
        a10 += e1 * w0; a11 += e1 * w1;
    }

    const int rA = r0 + i0, rB = r0 + i1;
    const int nA = n0 + j,  nB = n0 + j + 32;
    if (rA < V_POI) {
        if (nA < 1032) store_tl(rA, nA, a00);
        if (nB < 1032) store_tl(rA, nB, a01);
    }
    if (rB < V_POI) {
        if (nA < 1032) store_tl(rB, nA, a10);
        if (nB < 1032) store_tl(rB, nB, a11);
    }
}

// ---------------------------------------------------------------------------
// Build kernel B: hour*weekday combo rows (168), K=200 in two 100-passes.
// ---------------------------------------------------------------------------
__global__ void build_hw_kernel(const float* __restrict__ emb_hour,
                                const float* __restrict__ emb_wd,
                                const float* __restrict__ W_poi,
                                const float* __restrict__ W_hour,
                                const float* __restrict__ W_wd) {
    __shared__ float Wst[100][65];
    __shared__ float Es[16][100];

    const int n0  = blockIdx.x * 64;
    const int r0  = blockIdx.y * 16;
    const int tid = threadIdx.y * 32 + threadIdx.x;

    const int j  = threadIdx.x;
    const int i0 = threadIdx.y;
    const int i1 = threadIdx.y + 8;

    float a00 = 0.f, a01 = 0.f, a10 = 0.f, a11 = 0.f;

    for (int seg = 0; seg < 2; seg++) {
        const int so = 100 + seg * 100;
        for (int idx = tid; idx < 64 * 100; idx += 256) {
            int c = idx / 100, d = idx - c * 100;
            Wst[d][c] = wload(W_poi, W_hour, W_wd, n0 + c, so, d);
        }
        for (int idx = tid; idx < 16 * 100; idx += 256) {
            int i = idx / 100, d = idx - i * 100;
            int cc = r0 + i;
            float v = 0.f;
            if (cc < N_HW) {
                int h = cc / V_WD, w = cc - h * V_WD;
                v = (seg == 0) ? emb_hour[h * D_EMB + d] : emb_wd[w * D_EMB + d];
            }
            Es[i][d] = v;
        }
        __syncthreads();

#pragma unroll 10
        for (int d = 0; d < 100; d++) {
            float w0 = Wst[d][j], w1 = Wst[d][j + 32];
            float e0 = Es[i0][d], e1 = Es[i1][d];
            a00 += e0 * w0; a01 += e0 * w1;
            a10 += e1 * w0; a11 += e1 * w1;
        }
        __syncthreads();
    }

    const int cA = r0 + i0, cB = r0 + i1;
    const int nA = n0 + j,  nB = n0 + j + 32;
    if (cA < N_HW) {
        if (nA < 1032) store_tl(V_POI + cA, nA, a00);
        if (nB < 1032) store_tl(V_POI + cA, nB, a01);
    }
    if (cB < N_HW) {
        if (nA < 1032) store_tl(V_POI + cB, nA, a10);
        if (nB < 1032) store_tl(V_POI + cB, nB, a11);
    }
}

// ---------------------------------------------------------------------------
// Prep: per-sample row byte-offsets + (T, 1/e).
// ---------------------------------------------------------------------------
__global__ void prep_off_kernel(const int* __restrict__ x,
                                const int* __restrict__ lens, int B) {
    const int s = blockIdx.x * 256 + threadIdx.x;
    if (s >= B) return;
    const int* xp = x + s * (L_WIN * 3);
    int* op = g_off + s * 24;
#pragma unroll
    for (int l = 0; l < L_WIN; l++) {
        int p = xp[3 * l + 0];
        int h = xp[3 * l + 1];
        int w = xp[3 * l + 2];
        op[2 * l]     = p * 128;                              // row bytes
        op[2 * l + 1] = (V_POI + h * V_WD + w) * 128;
    }
    int e = min(max(lens[s], 1), L_WIN);
    op[20] = 2 * e;
    op[21] = __float_as_int(1.0f / (float)e);
}

// ---------------------------------------------------------------------------
// Main gather: grid (16 tiles x 9 chunks) = 144 blocks -> ONE block per SM,
// so each SM's L1 working set is exactly one contiguous 149.5KB tile slice.
// 1024 threads = 32 warps; warp-per-sample; lane owns 2 cols (half2).
// Rows summed in fp16 quads (HADD2) then flushed to fp32 (T=2e is even).
// ---------------------------------------------------------------------------
__global__ void __launch_bounds__(1024, 1)
cbow_gather_kernel(const float* __restrict__ b_poi,
                   const float* __restrict__ b_hour,
                   float* __restrict__ out,
                   int B) {
    const int ti    = blockIdx.x;            // column tile
    const int chunk = blockIdx.y;            // strided sample set
    const int w     = threadIdx.x >> 5;      // warp 0..31
    const int lane  = threadIdx.x & 31;

    const char* tl = reinterpret_cast<const char*>(g_TLt)
                   + (size_t)ti * (NROWS * TCOLS * 2) + lane * 4;

    // per-lane fixed output mapping + bias
    const int n0 = ti * TCOLS + lane * 2;    // even; never straddles poi/hour
    float bx, by; float* dstbase; int stride;
    if (n0 < V_POI) {
        bx = b_poi[n0]; by = b_poi[n0 + 1];
        dstbase = out + n0;              stride = V_POI;
    } else {
        bx = b_hour[n0 - V_POI]; by = b_hour[n0 - V_POI + 1];
        dstbase = out + (size_t)B * V_POI + (n0 - V_POI); stride = V_HOUR;
    }

    for (int i = w;; i += 32) {
        const int s = chunk + i * NCHUNK;
        if (s >= B) break;

        const int* op = g_off + s * 24;
        int v = (lane < 22) ? op[lane] : 0;
        const int   T   = __shfl_sync(0xffffffffu, v, 20);
        const float inv = __int_as_float(__shfl_sync(0xffffffffu, v, 21));

        float accx = 0.f, accy = 0.f;
        int t = 0;
        for (; t + 4 <= T; t += 4) {
            int o0 = __shfl_sync(0xffffffffu, v, t);
            int o1 = __shfl_sync(0xffffffffu, v, t + 1);
            int o2 = __shfl_sync(0xffffffffu, v, t + 2);
            int o3 = __shfl_sync(0xffffffffu, v, t + 3);
            __half2 a = *reinterpret_cast<const __half2*>(tl + o0);
            __half2 b = *reinterpret_cast<const __half2*>(tl + o1);
            __half2 c = *reinterpret_cast<const __half2*>(tl + o2);
            __half2 d = *reinterpret_cast<const __half2*>(tl + o3);
            __half2 h = __hadd2(__hadd2(a, b), __hadd2(c, d));
            float2 f = __half22float2(h);
            accx += f.x; accy += f.y;
        }
        if (t < T) {                         // remaining pair (T even)
            int o0 = __shfl_sync(0xffffffffu, v, t);
            int o1 = __shfl_sync(0xffffffffu, v, t + 1);
            __half2 h = __hadd2(*reinterpret_cast<const __half2*>(tl + o0),
                                *reinterpret_cast<const __half2*>(tl + o1));
            float2 f = __half22float2(h);
            accx += f.x; accy += f.y;
        }

        float2 r;
        r.x = accx * inv + bx;
        r.y = accy * inv + by;
        *reinterpret_cast<float2*>(dstbase + (size_t)s * stride) = r;
    }
}

// ---------------------------------------------------------------------------
// Weekday head: 8 threads per sample over the compact fp32 TLwd table.
// ---------------------------------------------------------------------------
__global__ void wd_kernel(const int* __restrict__ x,
                          const int* __restrict__ lens,
                          const float* __restrict__ b_wd,
                          float* __restrict__ out,
                          int B) {
    const int g = blockIdx.x * 32 + (threadIdx.x >> 3);
    const int k = threadIdx.x & 7;
    if (g >= B) return;

    int e = min(max(lens[g], 1), L_WIN);
    const int* xp = x + g * (L_WIN * 3);

    float acc = 0.f;
    for (int t = 0; t < e; t++) {
        int p = xp[t * 3 + 0];
        int h = xp[t * 3 + 1];
        int w = xp[t * 3 + 2];
        acc += g_TLwd[p * 8 + k];
        acc += g_TLwd[(V_POI + h * V_WD + w) * 8 + k];
    }
    if (k < V_WD)
        out[(size_t)B * (V_POI + V_HOUR) + (size_t)g * V_WD + k] =
            acc / (float)e + b_wd[k];
}

// ---------------------------------------------------------------------------
// Launch
// ---------------------------------------------------------------------------
extern "C" void kernel_launch(void* const* d_in, const int* in_sizes, int n_in,
                              void* d_out, int out_size) {
    const int*   x        = (const int*)  d_in[0];
    const int*   lens     = (const int*)  d_in[1];
    const float* emb_poi  = (const float*)d_in[2];
    const float* emb_hour = (const float*)d_in[3];
    const float* emb_wd   = (const float*)d_in[4];
    const float* W_poi    = (const float*)d_in[5];
    const float* b_poi    = (const float*)d_in[6];
    const float* W_hour   = (const float*)d_in[7];
    const float* b_hour   = (const float*)d_in[8];
    const float* W_wd     = (const float*)d_in[9];
    const float* b_wd     = (const float*)d_in[10];

    const int B = in_sizes[0] / (L_WIN * 3);

    build_poi_kernel<<<dim3(17, (V_POI + 15) / 16), dim3(32, 8)>>>(
        emb_poi, W_poi, W_hour, W_wd);
    build_hw_kernel<<<dim3(17, (N_HW + 15) / 16), dim3(32, 8)>>>(
        emb_hour, emb_wd, W_poi, W_hour, W_wd);
    prep_off_kernel<<<(B + 255) / 256, 256>>>(x, lens, B);

    cbow_gather_kernel<<<dim3(NTILES, NCHUNK), 1024>>>(b_poi, b_hour,
                                                       (float*)d_out, B);
    wd_kernel<<<(B + 31) / 32, 256>>>(x, lens, b_wd, (float*)d_out, B);
}

// round 10
// speedup vs baseline: 1.3467x; 1.3467x over previous
#include <cuda_runtime.h>
#include <cuda_fp16.h>

// Problem constants (fixed by the dataset)
#define L_WIN   10
#define D_EMB   100
#define V_POI   1000
#define V_HOUR  24
#define V_WD    7
#define N_HW    (V_HOUR * V_WD)           // 168 hour*weekday combo rows
#define NROWS   (V_POI + N_HW)            // 1168 token rows (for wd table)
#define NTILES  4                         // 4 column tiles x 256 cols = 1024
#define TCOLS   256
#define GY      74                        // grid.y: 4*74=296 blocks = 2/SM
#define BTHREADS 768                      // 24 warps

// Column-tiled poi token-logit table (fp16): [tile][1000 rows][256 cols].
// Streams from L2 (2.05MB, L2-resident).
__device__ __align__(128) __half g_poi_t[NTILES * V_POI * TCOLS];   // 2.05 MB
// Column-tiled hour*weekday combo table (fp16): [tile][168 rows][256 cols].
// One tile slice = 86KB -> loaded into SMEM by each gather block.
__device__ __align__(128) __half g_hw_t[NTILES * N_HW * TCOLS];     // 344 KB

// Compact weekday-logit table (fp32): cols [0,7) weekday logits, col 7 pad.
__device__ __align__(128) float g_TLwd[NROWS * 8];                  // 37 KB

// Per-sample meta (stride 24 ints):
// [0..9]=poi row byte-offsets (p*512), [10..19]=hw row byte-offsets (c*512),
// [20]=e, [21]=1/e bits.
__device__ int g_off[65536 * 24];                                   // 6.3 MB

#define HW_SLICE_BYTES (N_HW * TCOLS * 2)   // 86016

// ---------------------------------------------------------------------------
__device__ __forceinline__ float wload(const float* __restrict__ W_poi,
                                       const float* __restrict__ W_hour,
                                       const float* __restrict__ W_wd,
                                       int n, int so, int d) {
    if (n < V_POI)          return W_poi[n * 300 + so + d];
    if (n < V_POI + V_HOUR) return W_hour[(n - V_POI) * 300 + so + d];
    if (n < 1031)           return W_wd[(n - 1024) * 300 + so + d];
    return 0.f;
}

__device__ __forceinline__ void store_tl(int r, int n, float v) {
    if (n < 1024) {
        int tile = n >> 8, c = n & 255;
        if (r < V_POI)
            g_poi_t[(tile * V_POI + r) * TCOLS + c] = __float2half_rn(v);
        else
            g_hw_t[(tile * N_HW + (r - V_POI)) * TCOLS + c] = __float2half_rn(v);
    } else if (n < 1032) {
        g_TLwd[r * 8 + (n - 1024)] = v;
    }
}

// ---------------------------------------------------------------------------
// Build kernel A: poi rows (K=100). Tile 16 rows x 64 cols, 2x2 per thread.
// ---------------------------------------------------------------------------
__global__ void build_poi_kernel(const float* __restrict__ emb_poi,
                                 const float* __restrict__ W_poi,
                                 const float* __restrict__ W_hour,
                                 const float* __restrict__ W_wd) {
    __shared__ float Wst[100][65];
    __shared__ float Es[16][100];

    const int n0  = blockIdx.x * 64;
    const int r0  = blockIdx.y * 16;
    const int tid = threadIdx.y * 32 + threadIdx.x;

    for (int idx = tid; idx < 64 * 100; idx += 256) {
        int c = idx / 100, d = idx - c * 100;
        Wst[d][c] = wload(W_poi, W_hour, W_wd, n0 + c, 0, d);
    }
    for (int idx = tid; idx < 16 * 100; idx += 256) {
        int i = idx / 100, d = idx - i * 100;
        int r = r0 + i;
        Es[i][d] = (r < V_POI) ? emb_poi[r * D_EMB + d] : 0.f;
    }
    __syncthreads();

    const int j  = threadIdx.x;
    const int i0 = threadIdx.y;
    const int i1 = threadIdx.y + 8;

    float a00 = 0.f, a01 = 0.f, a10 = 0.f, a11 = 0.f;
#pragma unroll 10
    for (int d = 0; d < 100; d++) {
        float w0 = Wst[d][j], w1 = Wst[d][j + 32];
        float e0 = Es[i0][d], e1 = Es[i1][d];
        a00 += e0 * w0; a01 += e0 * w1;
        a10 += e1 * w0; a11 += e1 * w1;
    }

    const int rA = r0 + i0, rB = r0 + i1;
    const int nA = n0 + j,  nB = n0 + j + 32;
    if (rA < V_POI) {
        if (nA < 1032) store_tl(rA, nA, a00);
        if (nB < 1032) store_tl(rA, nB, a01);
    }
    if (rB < V_POI) {
        if (nA < 1032) store_tl(rB, nA, a10);
        if (nB < 1032) store_tl(rB, nB, a11);
    }
}

// ---------------------------------------------------------------------------
// Build kernel B: hour*weekday combo rows (168), K=200 in two 100-passes.
// ---------------------------------------------------------------------------
__global__ void build_hw_kernel(const float* __restrict__ emb_hour,
                                const float* __restrict__ emb_wd,
                                const float* __restrict__ W_poi,
                                const float* __restrict__ W_hour,
                                const float* __restrict__ W_wd) {
    __shared__ float Wst[100][65];
    __shared__ float Es[16][100];

    const int n0  = blockIdx.x * 64;
    const int r0  = blockIdx.y * 16;
    const int tid = threadIdx.y * 32 + threadIdx.x;

    const int j  = threadIdx.x;
    const int i0 = threadIdx.y;
    const int i1 = threadIdx.y + 8;

    float a00 = 0.f, a01 = 0.f, a10 = 0.f, a11 = 0.f;

    for (int seg = 0; seg < 2; seg++) {
        const int so = 100 + seg * 100;
        for (int idx = tid; idx < 64 * 100; idx += 256) {
            int c = idx / 100, d = idx - c * 100;
            Wst[d][c] = wload(W_poi, W_hour, W_wd, n0 + c, so, d);
        }
        for (int idx = tid; idx < 16 * 100; idx += 256) {
            int i = idx / 100, d = idx - i * 100;
            int cc = r0 + i;
            float v = 0.f;
            if (cc < N_HW) {
                int h = cc / V_WD, w = cc - h * V_WD;
                v = (seg == 0) ? emb_hour[h * D_EMB + d] : emb_wd[w * D_EMB + d];
            }
            Es[i][d] = v;
        }
        __syncthreads();

#pragma unroll 10
        for (int d = 0; d < 100; d++) {
            float w0 = Wst[d][j], w1 = Wst[d][j + 32];
            float e0 = Es[i0][d], e1 = Es[i1][d];
            a00 += e0 * w0; a01 += e0 * w1;
            a10 += e1 * w0; a11 += e1 * w1;
        }
        __syncthreads();
    }

    const int cA = r0 + i0, cB = r0 + i1;
    const int nA = n0 + j,  nB = n0 + j + 32;
    if (cA < N_HW) {
        if (nA < 1032) store_tl(V_POI + cA, nA, a00);
        if (nB < 1032) store_tl(V_POI + cA, nB, a01);
    }
    if (cB < N_HW) {
        if (nA < 1032) store_tl(V_POI + cB, nA, a10);
        if (nB < 1032) store_tl(V_POI + cB, nB, a11);
    }
}

// ---------------------------------------------------------------------------
// Prep: per-sample row byte-offsets + (e, 1/e).
// ---------------------------------------------------------------------------
__global__ void prep_off_kernel(const int* __restrict__ x,
                                const int* __restrict__ lens, int B) {
    const int s = blockIdx.x * 256 + threadIdx.x;
    if (s >= B) return;
    const int* xp = x + s * (L_WIN * 3);
    int* op = g_off + s * 24;
#pragma unroll
    for (int l = 0; l < L_WIN; l++) {
        int p = xp[3 * l + 0];
        int h = xp[3 * l + 1];
        int w = xp[3 * l + 2];
        op[l]      = p * (TCOLS * 2);                   // poi row bytes (512)
        op[10 + l] = (h * V_WD + w) * (TCOLS * 2);      // hw row bytes (512)
    }
    int e = min(max(lens[s], 1), L_WIN);
    op[20] = e;
    op[21] = __float_as_int(1.0f / (float)e);
}

// ---------------------------------------------------------------------------
// Main gather: grid (4 tiles x 74 chunks) = 296 blocks (2/SM), 768 threads.
// Block loads its 86KB hw tile slice into SMEM once; poi rows stream from L2.
// Warp per sample: lane owns 8 cols (16B). fp16 adds <=2 deep, then fp32.
// ---------------------------------------------------------------------------
__global__ void __launch_bounds__(BTHREADS, 2)
cbow_gather_kernel(const float* __restrict__ b_poi,
                   const float* __restrict__ b_hour,
                   float* __restrict__ out,
                   int B) {
    extern __shared__ __align__(16) char s_hw[];   // 86016 B hw tile slice

    const int ti = blockIdx.x;                     // column tile 0..3

    {   // cooperative slice load: 5376 uint4
        const uint4* src = reinterpret_cast<const uint4*>(
            reinterpret_cast<const char*>(g_hw_t) + (size_t)ti * HW_SLICE_BYTES);
        uint4* dst = reinterpret_cast<uint4*>(s_hw);
        for (int i = threadIdx.x; i < HW_SLICE_BYTES / 16; i += BTHREADS)
            dst[i] = src[i];
    }
    __syncthreads();

    const int w    = threadIdx.x >> 5;             // warp 0..23
    const int lane = threadIdx.x & 31;
    const int gw   = blockIdx.y * (BTHREADS / 32) + w;   // 0..1775
    const int nwarps = GY * (BTHREADS / 32);             // 1776

    const char* poi_base = reinterpret_cast<const char*>(g_poi_t)
                         + (size_t)ti * (V_POI * TCOLS * 2) + lane * 16;
    const char* hw_base  = s_hw + lane * 16;

    const int n0 = ti * TCOLS + lane * 8;          // 8 output cols per lane

    // fixed per-lane output mapping (boundary 1000 is 8-aligned: no straddle)
    const float* bias;
    float* dstbase; int stride;
    if (n0 < V_POI) {
        bias = b_poi + n0;
        dstbase = out + n0;                     stride = V_POI;
    } else {
        bias = b_hour + (n0 - V_POI);
        dstbase = out + (size_t)B * V_POI + (n0 - V_POI); stride = V_HOUR;
    }

    for (int s = gw; s < B; s += nwarps) {
        const int* op = g_off + s * 24;
        int v = (lane < 22) ? op[lane] : 0;
        const int   e   = __shfl_sync(0xffffffffu, v, 20);
        const float inv = __int_as_float(__shfl_sync(0xffffffffu, v, 21));

        float acc[8];
#pragma unroll
        for (int i = 0; i < 8; i++) acc[i] = 0.f;

        int t = 0;
#pragma unroll 2
        for (; t + 2 <= e; t += 2) {
            int po0 = __shfl_sync(0xffffffffu, v, t);
            int po1 = __shfl_sync(0xffffffffu, v, t + 1);
            int ho0 = __shfl_sync(0xffffffffu, v, 10 + t);
            int ho1 = __shfl_sync(0xffffffffu, v, 10 + t + 1);
            uint4 P0 = *reinterpret_cast<const uint4*>(poi_base + po0);
            uint4 P1 = *reinterpret_cast<const uint4*>(poi_base + po1);
            uint4 H0 = *reinterpret_cast<const uint4*>(hw_base + ho0);
            uint4 H1 = *reinterpret_cast<const uint4*>(hw_base + ho1);
            const unsigned* p0 = &P0.x; const unsigned* p1 = &P1.x;
            const unsigned* h0 = &H0.x; const unsigned* h1 = &H1.x;
#pragma unroll
            for (int i = 0; i < 4; i++) {
                __half2 a = __hadd2(*reinterpret_cast<const __half2*>(&p0[i]),
                                    *reinterpret_cast<const __half2*>(&h0[i]));
                __half2 b = __hadd2(*reinterpret_cast<const __half2*>(&p1[i]),
                                    *reinterpret_cast<const __half2*>(&h1[i]));
                float2 f = __half22float2(__hadd2(a, b));
                acc[2 * i]     += f.x;
                acc[2 * i + 1] += f.y;
            }
        }
        if (t < e) {                               // odd tail position
            int po = __shfl_sync(0xffffffffu, v, t);
            int ho = __shfl_sync(0xffffffffu, v, 10 + t);
            uint4 P = *reinterpret_cast<const uint4*>(poi_base + po);
            uint4 H = *reinterpret_cast<const uint4*>(hw_base + ho);
            const unsigned* p = &P.x; const unsigned* h = &H.x;
#pragma unroll
            for (int i = 0; i < 4; i++) {
                __half2 q = __hadd2(*reinterpret_cast<const __half2*>(&p[i]),
                                    *reinterpret_cast<const __half2*>(&h[i]));
                float2 f = __half22float2(q);
                acc[2 * i]     += f.x;
                acc[2 * i + 1] += f.y;
            }
        }

        float4 bv0 = *reinterpret_cast<const float4*>(bias);
        float4 bv1 = *reinterpret_cast<const float4*>(bias + 4);
        float4 o0, o1;
        o0.x = acc[0] * inv + bv0.x; o0.y = acc[1] * inv + bv0.y;
        o0.z = acc[2] * inv + bv0.z; o0.w = acc[3] * inv + bv0.w;
        o1.x = acc[4] * inv + bv1.x; o1.y = acc[5] * inv + bv1.y;
        o1.z = acc[6] * inv + bv1.z; o1.w = acc[7] * inv + bv1.w;
        float* dp = dstbase + (size_t)s * stride;
        *reinterpret_cast<float4*>(dp)     = o0;
        *reinterpret_cast<float4*>(dp + 4) = o1;
    }
}

// ---------------------------------------------------------------------------
// Weekday head: 8 threads per sample over the compact fp32 TLwd table.
// ---------------------------------------------------------------------------
__global__ void wd_kernel(const int* __restrict__ x,
                          const int* __restrict__ lens,
                          const float* __restrict__ b_wd,
                          float* __restrict__ out,
                          int B) {
    const int g = blockIdx.x * 32 + (threadIdx.x >> 3);
    const int k = threadIdx.x & 7;
    if (g >= B) return;

    int e = min(max(lens[g], 1), L_WIN);
    const int* xp = x + g * (L_WIN * 3);

    float acc = 0.f;
    for (int t = 0; t < e; t++) {
        int p = xp[t * 3 + 0];
        int h = xp[t * 3 + 1];
        int w = xp[t * 3 + 2];
        acc += g_TLwd[p * 8 + k];
        acc += g_TLwd[(V_POI + h * V_WD + w) * 8 + k];
    }
    if (k < V_WD)
        out[(size_t)B * (V_POI + V_HOUR) + (size_t)g * V_WD + k] =
            acc / (float)e + b_wd[k];
}

// ---------------------------------------------------------------------------
// Launch
// ---------------------------------------------------------------------------
extern "C" void kernel_launch(void* const* d_in, const int* in_sizes, int n_in,
                              void* d_out, int out_size) {
    const int*   x        = (const int*)  d_in[0];
    const int*   lens     = (const int*)  d_in[1];
    const float* emb_poi  = (const float*)d_in[2];
    const float* emb_hour = (const float*)d_in[3];
    const float* emb_wd   = (const float*)d_in[4];
    const float* W_poi    = (const float*)d_in[5];
    const float* b_poi    = (const float*)d_in[6];
    const float* W_hour   = (const float*)d_in[7];
    const float* b_hour   = (const float*)d_in[8];
    const float* W_wd     = (const float*)d_in[9];
    const float* b_wd     = (const float*)d_in[10];

    const int B = in_sizes[0] / (L_WIN * 3);

    // Unconditional (no static state): idempotent host-side attribute set.
    cudaFuncSetAttribute(cbow_gather_kernel,
                         cudaFuncAttributeMaxDynamicSharedMemorySize,
                         HW_SLICE_BYTES);

    build_poi_kernel<<<dim3(17, (V_POI + 15) / 16), dim3(32, 8)>>>(
        emb_poi, W_poi, W_hour, W_wd);
    build_hw_kernel<<<dim3(17, (N_HW + 15) / 16), dim3(32, 8)>>>(
        emb_hour, emb_wd, W_poi, W_hour, W_wd);
    prep_off_kernel<<<(B + 255) / 256, 256>>>(x, lens, B);

    cbow_gather_kernel<<<dim3(NTILES, GY), BTHREADS, HW_SLICE_BYTES>>>(
        b_poi, b_hour, (float*)d_out, B);
    wd_kernel<<<(B + 31) / 32, 256>>>(x, lens, b_wd, (float*)d_out, B);
}

// round 11
// speedup vs baseline: 1.5095x; 1.1209x over previous
#include <cuda_runtime.h>
#include <cuda_fp16.h>

// Problem constants (fixed by the dataset)
#define L_WIN   10
#define D_EMB   100
#define V_POI   1000
#define V_HOUR  24
#define V_WD    7
#define N_HW    (V_HOUR * V_WD)           // 168 hour*weekday combo rows
#define NROWS   (V_POI + N_HW)            // 1168 token rows (for wd table)
#define NTILES  4                         // 4 column tiles x 256 cols = 1024
#define TCOLS   256
#define GY      74                        // gather grid.y: 4*74=296 blocks
#define BTHREADS 768                      // 24 warps

// Column-tiled poi token-logit table (fp16): [tile][1000 rows][256 cols].
__device__ __align__(128) __half g_poi_t[NTILES * V_POI * TCOLS];   // 2.05 MB
// Column-tiled hour*weekday combo table (fp16): [tile][168 rows][256 cols].
__device__ __align__(128) __half g_hw_t[NTILES * N_HW * TCOLS];     // 344 KB
// Compact weekday-logit table (fp32): cols [0,7) weekday logits, col 7 pad.
__device__ __align__(128) float g_TLwd[NROWS * 8];                  // 37 KB
// Per-sample meta (stride 24 ints):
// [0..9]=poi row byte-offsets, [10..19]=hw row byte-offsets, [20]=e, [21]=1/e.
__device__ int g_off[65536 * 24];                                   // 6.3 MB

#define HW_SLICE_BYTES (N_HW * TCOLS * 2)   // 86016

// ---------------------------------------------------------------------------
__device__ __forceinline__ float wload(const float* __restrict__ W_poi,
                                       const float* __restrict__ W_hour,
                                       const float* __restrict__ W_wd,
                                       int n, int so, int d) {
    if (n < V_POI)          return W_poi[n * 300 + so + d];
    if (n < V_POI + V_HOUR) return W_hour[(n - V_POI) * 300 + so + d];
    if (n < 1031)           return W_wd[(n - 1024) * 300 + so + d];
    return 0.f;
}

__device__ __forceinline__ void store_tl(int r, int n, float v) {
    if (n < 1024) {
        int tile = n >> 8, c = n & 255;
        if (r < V_POI)
            g_poi_t[(tile * V_POI + r) * TCOLS + c] = __float2half_rn(v);
        else
            g_hw_t[(tile * N_HW + (r - V_POI)) * TCOLS + c] = __float2half_rn(v);
    } else if (n < 1032) {
        g_TLwd[r * 8 + (n - 1024)] = v;
    }
}

// ---------------------------------------------------------------------------
// Fused setup kernel: grid (17, 90), 256 threads.
//   y in [0,63)  : poi build tile  (rows y*16..+16, cols x*64..+64)
//   y in [63,74) : hw  build tile  (combos (y-63)*16..+16)
//   y in [74,90) : prep blocks     (272 blocks cover 65536 samples)
// Shared memory union: build uses Wst(26000B)+Es(6400B); prep uses 24576B.
// ---------------------------------------------------------------------------
__global__ void __launch_bounds__(256)
setup_kernel(const int* __restrict__ x,
             const int* __restrict__ lens,
             const float* __restrict__ emb_poi,
             const float* __restrict__ emb_hour,
             const float* __restrict__ emb_wd,
             const float* __restrict__ W_poi,
             const float* __restrict__ W_hour,
             const float* __restrict__ W_wd,
             int B) {
    __shared__ __align__(16) char sbuf[32400];

    const int y   = blockIdx.y;
    const int tid = threadIdx.y * 32 + threadIdx.x;

    if (y < 74) {
        // ---------------- build branch ----------------
        float (*Wst)[65] = reinterpret_cast<float (*)[65]>(sbuf);          // [100][65]
        float (*Es)[100] = reinterpret_cast<float (*)[100]>(sbuf + 26000); // [16][100]

        const int n0 = blockIdx.x * 64;
        const int j  = threadIdx.x;
        const int i0 = threadIdx.y;
        const int i1 = threadIdx.y + 8;

        if (y < 63) {
            // poi rows, K=100
            const int r0 = y * 16;
            for (int idx = tid; idx < 64 * 100; idx += 256) {
                int c = idx / 100, d = idx - c * 100;
                Wst[d][c] = wload(W_poi, W_hour, W_wd, n0 + c, 0, d);
            }
            for (int idx = tid; idx < 16 * 100; idx += 256) {
                int i = idx / 100, d = idx - i * 100;
                int r = r0 + i;
                Es[i][d] = (r < V_POI) ? emb_poi[r * D_EMB + d] : 0.f;
            }
            __syncthreads();

            float a00 = 0.f, a01 = 0.f, a10 = 0.f, a11 = 0.f;
#pragma unroll 10
            for (int d = 0; d < 100; d++) {
                float w0 = Wst[d][j], w1 = Wst[d][j + 32];
                float e0 = Es[i0][d], e1 = Es[i1][d];
                a00 += e0 * w0; a01 += e0 * w1;
                a10 += e1 * w0; a11 += e1 * w1;
            }
            const int rA = r0 + i0, rB = r0 + i1;
            const int nA = n0 + j,  nB = n0 + j + 32;
            if (rA < V_POI) {
                if (nA < 1032) store_tl(rA, nA, a00);
                if (nB < 1032) store_tl(rA, nB, a01);
            }
            if (rB < V_POI) {
                if (nA < 1032) store_tl(rB, nA, a10);
                if (nB < 1032) store_tl(rB, nB, a11);
            }
        } else {
            // hw combo rows, K=200 in two 100-passes
            const int r0 = (y - 63) * 16;
            float a00 = 0.f, a01 = 0.f, a10 = 0.f, a11 = 0.f;
            for (int seg = 0; seg < 2; seg++) {
                const int so = 100 + seg * 100;
                for (int idx = tid; idx < 64 * 100; idx += 256) {
                    int c = idx / 100, d = idx - c * 100;
                    Wst[d][c] = wload(W_poi, W_hour, W_wd, n0 + c, so, d);
                }
                for (int idx = tid; idx < 16 * 100; idx += 256) {
                    int i = idx / 100, d = idx - i * 100;
                    int cc = r0 + i;
                    float v = 0.f;
                    if (cc < N_HW) {
                        int h = cc / V_WD, w = cc - h * V_WD;
                        v = (seg == 0) ? emb_hour[h * D_EMB + d]
                                       : emb_wd[w * D_EMB + d];
                    }
                    Es[i][d] = v;
                }
                __syncthreads();
#pragma unroll 10
                for (int d = 0; d < 100; d++) {
                    float w0 = Wst[d][j], w1 = Wst[d][j + 32];
                    float e0 = Es[i0][d], e1 = Es[i1][d];
                    a00 += e0 * w0; a01 += e0 * w1;
                    a10 += e1 * w0; a11 += e1 * w1;
                }
                __syncthreads();
            }
            const int cA = r0 + i0, cB = r0 + i1;
            const int nA = n0 + j,  nB = n0 + j + 32;
            if (cA < N_HW) {
                if (nA < 1032) store_tl(V_POI + cA, nA, a00);
                if (nB < 1032) store_tl(V_POI + cA, nB, a01);
            }
            if (cB < N_HW) {
                if (nA < 1032) store_tl(V_POI + cB, nA, a10);
                if (nB < 1032) store_tl(V_POI + cB, nB, a11);
            }
        }
    } else {
        // ---------------- prep branch (coalesced via smem staging) --------
        int* obuf = reinterpret_cast<int*>(sbuf);       // [256][24]
        const int pid = (y - 74) * 17 + blockIdx.x;     // 0..271
        const int s0  = pid * 256;
        if (s0 >= B) return;
        const int nv = min(256, B - s0);

        if (tid < nv) {
            const int s = s0 + tid;
            const int* xp = x + s * (L_WIN * 3);
            int* op = obuf + tid * 24;
#pragma unroll
            for (int l = 0; l < L_WIN; l++) {
                int p = __ldg(xp + 3 * l + 0);
                int h = __ldg(xp + 3 * l + 1);
                int w = __ldg(xp + 3 * l + 2);
                op[l]      = p * (TCOLS * 2);
                op[10 + l] = (h * V_WD + w) * (TCOLS * 2);
            }
            int e = min(max(lens[s], 1), L_WIN);
            op[20] = e;
            op[21] = __float_as_int(1.0f / (float)e);
            op[22] = 0;
            op[23] = 0;
        }
        __syncthreads();

        const int total = nv * 24;
        int* dst = g_off + (size_t)s0 * 24;
        for (int i = tid; i < total; i += 256)
            dst[i] = obuf[i];
    }
}

// ---------------------------------------------------------------------------
// Main gather: grid (4 tiles x 74 chunks) = 296 blocks (2/SM), 768 threads.
// Block loads its 86KB hw tile slice into SMEM once; poi rows stream from L2.
// Warp per sample: lane owns 8 cols (16B). fp16 adds <=2 deep, then fp32.
// ---------------------------------------------------------------------------
__global__ void __launch_bounds__(BTHREADS, 2)
cbow_gather_kernel(const float* __restrict__ b_poi,
                   const float* __restrict__ b_hour,
                   float* __restrict__ out,
                   int B) {
    extern __shared__ __align__(16) char s_hw[];   // 86016 B hw tile slice

    const int ti = blockIdx.x;                     // column tile 0..3

    {   // cooperative slice load: 5376 uint4
        const uint4* src = reinterpret_cast<const uint4*>(
            reinterpret_cast<const char*>(g_hw_t) + (size_t)ti * HW_SLICE_BYTES);
        uint4* dst = reinterpret_cast<uint4*>(s_hw);
        for (int i = threadIdx.x; i < HW_SLICE_BYTES / 16; i += BTHREADS)
            dst[i] = src[i];
    }
    __syncthreads();

    const int w    = threadIdx.x >> 5;             // warp 0..23
    const int lane = threadIdx.x & 31;
    const int gw   = blockIdx.y * (BTHREADS / 32) + w;   // 0..1775
    const int nwarps = GY * (BTHREADS / 32);             // 1776

    const char* poi_base = reinterpret_cast<const char*>(g_poi_t)
                         + (size_t)ti * (V_POI * TCOLS * 2) + lane * 16;
    const char* hw_base  = s_hw + lane * 16;

    const int n0 = ti * TCOLS + lane * 8;          // 8 output cols per lane

    // fixed per-lane output mapping (boundary 1000 is 8-aligned: no straddle)
    const float* bias;
    float* dstbase; int stride;
    if (n0 < V_POI) {
        bias = b_poi + n0;
        dstbase = out + n0;                     stride = V_POI;
    } else {
        bias = b_hour + (n0 - V_POI);
        dstbase = out + (size_t)B * V_POI + (n0 - V_POI); stride = V_HOUR;
    }

    for (int s = gw; s < B; s += nwarps) {
        const int* op = g_off + s * 24;
        int v = (lane < 22) ? op[lane] : 0;
        const int   e   = __shfl_sync(0xffffffffu, v, 20);
        const float inv = __int_as_float(__shfl_sync(0xffffffffu, v, 21));

        float acc[8];
#pragma unroll
        for (int i = 0; i < 8; i++) acc[i] = 0.f;

        int t = 0;
#pragma unroll 2
        for (; t + 2 <= e; t += 2) {
            int po0 = __shfl_sync(0xffffffffu, v, t);
            int po1 = __shfl_sync(0xffffffffu, v, t + 1);
            int ho0 = __shfl_sync(0xffffffffu, v, 10 + t);
            int ho1 = __shfl_sync(0xffffffffu, v, 10 + t + 1);
            uint4 P0 = *reinterpret_cast<const uint4*>(poi_base + po0);
            uint4 P1 = *reinterpret_cast<const uint4*>(poi_base + po1);
            uint4 H0 = *reinterpret_cast<const uint4*>(hw_base + ho0);
            uint4 H1 = *reinterpret_cast<const uint4*>(hw_base + ho1);
            const unsigned* p0 = &P0.x; const unsigned* p1 = &P1.x;
            const unsigned* h0 = &H0.x; const unsigned* h1 = &H1.x;
#pragma unroll
            for (int i = 0; i < 4; i++) {
                __half2 a = __hadd2(*reinterpret_cast<const __half2*>(&p0[i]),
                                    *reinterpret_cast<const __half2*>(&h0[i]));
                __half2 b = __hadd2(*reinterpret_cast<const __half2*>(&p1[i]),
                                    *reinterpret_cast<const __half2*>(&h1[i]));
                float2 f = __half22float2(__hadd2(a, b));
                acc[2 * i]     += f.x;
                acc[2 * i + 1] += f.y;
            }
        }
        if (t < e) {                               // odd tail position
            int po = __shfl_sync(0xffffffffu, v, t);
            int ho = __shfl_sync(0xffffffffu, v, 10 + t);
            uint4 P = *reinterpret_cast<const uint4*>(poi_base + po);
            uint4 H = *reinterpret_cast<const uint4*>(hw_base + ho);
            const unsigned* p = &P.x; const unsigned* h = &H.x;
#pragma unroll
            for (int i = 0; i < 4; i++) {
                __half2 q = __hadd2(*reinterpret_cast<const __half2*>(&p[i]),
                                    *reinterpret_cast<const __half2*>(&h[i]));
                float2 f = __half22float2(q);
                acc[2 * i]     += f.x;
                acc[2 * i + 1] += f.y;
            }
        }

        float4 bv0 = *reinterpret_cast<const float4*>(bias);
        float4 bv1 = *reinterpret_cast<const float4*>(bias + 4);
        float4 o0, o1;
        o0.x = acc[0] * inv + bv0.x; o0.y = acc[1] * inv + bv0.y;
        o0.z = acc[2] * inv + bv0.z; o0.w = acc[3] * inv + bv0.w;
        o1.x = acc[4] * inv + bv1.x; o1.y = acc[5] * inv + bv1.y;
        o1.z = acc[6] * inv + bv1.z; o1.w = acc[7] * inv + bv1.w;
        float* dp = dstbase + (size_t)s * stride;
        *reinterpret_cast<float4*>(dp)     = o0;
        *reinterpret_cast<float4*>(dp + 4) = o1;
    }
}

// ---------------------------------------------------------------------------
// Weekday head: 8 threads per sample over the compact fp32 TLwd table.
// ---------------------------------------------------------------------------
__global__ void wd_kernel(const int* __restrict__ x,
                          const int* __restrict__ lens,
                          const float* __restrict__ b_wd,
                          float* __restrict__ out,
                          int B) {
    const int g = blockIdx.x * 32 + (threadIdx.x >> 3);
    const int k = threadIdx.x & 7;
    if (g >= B) return;

    int e = min(max(lens[g], 1), L_WIN);
    const int* xp = x + g * (L_WIN * 3);

    float acc = 0.f;
    for (int t = 0; t < e; t++) {
        int p = xp[t * 3 + 0];
        int h = xp[t * 3 + 1];
        int w = xp[t * 3 + 2];
        acc += g_TLwd[p * 8 + k];
        acc += g_TLwd[(V_POI + h * V_WD + w) * 8 + k];
    }
    if (k < V_WD)
        out[(size_t)B * (V_POI + V_HOUR) + (size_t)g * V_WD + k] =
            acc / (float)e + b_wd[k];
}

// ---------------------------------------------------------------------------
// Launch
// ---------------------------------------------------------------------------
extern "C" void kernel_launch(void* const* d_in, const int* in_sizes, int n_in,
                              void* d_out, int out_size) {
    const int*   x        = (const int*)  d_in[0];
    const int*   lens     = (const int*)  d_in[1];
    const float* emb_poi  = (const float*)d_in[2];
    const float* emb_hour = (const float*)d_in[3];
    const float* emb_wd   = (const float*)d_in[4];
    const float* W_poi    = (const float*)d_in[5];
    const float* b_poi    = (const float*)d_in[6];
    const float* W_hour   = (const float*)d_in[7];
    const float* b_hour   = (const float*)d_in[8];
    const float* W_wd     = (const float*)d_in[9];
    const float* b_wd     = (const float*)d_in[10];

    const int B = in_sizes[0] / (L_WIN * 3);

    cudaFuncSetAttribute(cbow_gather_kernel,
                         cudaFuncAttributeMaxDynamicSharedMemorySize,
                         HW_SLICE_BYTES);

    // One wide setup launch: builds (y<74) + prep (y>=74), all independent.
    setup_kernel<<<dim3(17, 90), dim3(32, 8)>>>(
        x, lens, emb_poi, emb_hour, emb_wd, W_poi, W_hour, W_wd, B);

    cbow_gather_kernel<<<dim3(NTILES, GY), BTHREADS, HW_SLICE_BYTES>>>(
        b_poi, b_hour, (float*)d_out, B);
    wd_kernel<<<(B + 31) / 32, 256>>>(x, lens, b_wd, (float*)d_out, B);
}

// round 13
// speedup vs baseline: 1.5229x; 1.0089x over previous
#include <cuda_runtime.h>
#include <cuda_fp16.h>

// Problem constants (fixed by the dataset)
#define L_WIN   10
#define D_EMB   100
#define V_POI   1000
#define V_HOUR  24
#define V_WD    7
#define N_HW    (V_HOUR * V_WD)           // 168 hour*weekday combo rows
#define NROWS   (V_POI + N_HW)            // 1168 token rows (for wd table)
#define NTILES  4                         // 4 column tiles x 256 cols = 1024
#define TCOLS   256
#define GY      74                        // gather grid.y: 4*74=296 blocks
#define BTHREADS 768                      // 24 warps

// Column-tiled poi token-logit table (fp16): [tile][1000 rows][256 cols].
__device__ __align__(128) __half g_poi_t[NTILES * V_POI * TCOLS];   // 2.05 MB
// Column-tiled hour*weekday combo table (fp16): [tile][168 rows][256 cols].
__device__ __align__(128) __half g_hw_t[NTILES * N_HW * TCOLS];     // 344 KB
// Compact weekday-logit table (fp32): cols [0,7) weekday logits, col 7 pad.
__device__ __align__(128) float g_TLwd[NROWS * 8];                  // 37 KB
// Per-sample meta (stride 24 ints):
// [0..9]=poi row byte-offsets, [10..19]=hw row byte-offsets, [20]=e, [21]=1/e.
__device__ int g_off[65536 * 24];                                   // 6.3 MB

#define HW_SLICE_BYTES (N_HW * TCOLS * 2)   // 86016

// setup grid.y split
#define YB_POI  32     // poi build: 32 blocks of 32 rows  (covers 1024>=1000)
#define YB_HW   6      // hw build:  6 blocks of 32 combos (covers 192>=168)
#define YB_PREP 16     // prep: 16*17=272 blocks of 256 samples
#define Y_TOTAL (YB_POI + YB_HW + YB_PREP)   // 54

// ---------------------------------------------------------------------------
__device__ __forceinline__ float wload(const float* __restrict__ W_poi,
                                       const float* __restrict__ W_hour,
                                       const float* __restrict__ W_wd,
                                       int n, int so, int d) {
    if (n < V_POI)          return W_poi[n * 300 + so + d];
    if (n < V_POI + V_HOUR) return W_hour[(n - V_POI) * 300 + so + d];
    if (n < 1031)           return W_wd[(n - 1024) * 300 + so + d];
    return 0.f;
}

__device__ __forceinline__ void store_tl(int r, int n, float v) {
    if (n < 1024) {
        int tile = n >> 8, c = n & 255;
        if (r < V_POI)
            g_poi_t[(tile * V_POI + r) * TCOLS + c] = __float2half_rn(v);
        else
            g_hw_t[(tile * N_HW + (r - V_POI)) * TCOLS + c] = __float2half_rn(v);
    } else if (n < 1032) {
        g_TLwd[r * 8 + (n - 1024)] = v;
    }
}

// ---------------------------------------------------------------------------
// Fused setup kernel: grid (17, 54), 256 threads (32x8).
//   y in [0,32)  : poi build tile (32 rows x 64 cols, 4x2 per thread)
//   y in [32,38) : hw  build tile (32 combos x 64 cols, 2 K-segments)
//   y in [38,54) : prep blocks    (272 blocks cover 65536 samples)
// Shared memory union: build Wst(26000B)+Es(12800B)=38800B; prep 24576B.
// ---------------------------------------------------------------------------
__global__ void __launch_bounds__(256)
setup_kernel(const int* __restrict__ x,
             const int* __restrict__ lens,
             const float* __restrict__ emb_poi,
             const float* __restrict__ emb_hour,
             const float* __restrict__ emb_wd,
             const float* __restrict__ W_poi,
             const float* __restrict__ W_hour,
             const float* __restrict__ W_wd,
             int B) {
    __shared__ __align__(16) char sbuf[38800];

    const int y   = blockIdx.y;
    const int tid = threadIdx.y * 32 + threadIdx.x;

    if (y < YB_POI + YB_HW) {
        // ---------------- build branch: 32 rows x 64 cols, 4x2/thread -----
        float (*Wst)[65]  = reinterpret_cast<float (*)[65]>(sbuf);          // [100][65]
        float (*Es)[100]  = reinterpret_cast<float (*)[100]>(sbuf + 26000); // [32][100]

        const int n0 = blockIdx.x * 64;
        const int j  = threadIdx.x;
        const int iy = threadIdx.y;        // rows iy, iy+8, iy+16, iy+24

        float a[4][2];
#pragma unroll
        for (int r = 0; r < 4; r++) { a[r][0] = 0.f; a[r][1] = 0.f; }

        if (y < YB_POI) {
            // poi rows, K=100
            const int r0 = y * 32;
            for (int idx = tid; idx < 64 * 100; idx += 256) {
                int c = idx / 100, d = idx - c * 100;
                Wst[d][c] = wload(W_poi, W_hour, W_wd, n0 + c, 0, d);
            }
            for (int idx = tid; idx < 32 * 100; idx += 256) {
                int i = idx / 100, d = idx - i * 100;
                int r = r0 + i;
                Es[i][d] = (r < V_POI) ? emb_poi[r * D_EMB + d] : 0.f;
            }
            __syncthreads();

#pragma unroll 5
            for (int d = 0; d < 100; d++) {
                float w0 = Wst[d][j], w1 = Wst[d][j + 32];
#pragma unroll
                for (int r = 0; r < 4; r++) {
                    float e = Es[iy + r * 8][d];
                    a[r][0] += e * w0;
                    a[r][1] += e * w1;
                }
            }
#pragma unroll
            for (int r = 0; r < 4; r++) {
                int row = r0 + iy + r * 8;
                if (row < V_POI) {
                    store_tl(row, n0 + j,      a[r][0]);
                    store_tl(row, n0 + j + 32, a[r][1]);
                }
            }
        } else {
            // hw combo rows, K=200 in two 100-passes
            const int r0 = (y - YB_POI) * 32;
            for (int seg = 0; seg < 2; seg++) {
                const int so = 100 + seg * 100;
                if (seg) __syncthreads();
                for (int idx = tid; idx < 64 * 100; idx += 256) {
                    int c = idx / 100, d = idx - c * 100;
                    Wst[d][c] = wload(W_poi, W_hour, W_wd, n0 + c, so, d);
                }
                for (int idx = tid; idx < 32 * 100; idx += 256) {
                    int i = idx / 100, d = idx - i * 100;
                    int cc = r0 + i;
                    float v = 0.f;
                    if (cc < N_HW) {
                        int h = cc / V_WD, w = cc - h * V_WD;
                        v = (seg == 0) ? emb_hour[h * D_EMB + d]
                                       : emb_wd[w * D_EMB + d];
                    }
                    Es[i][d] = v;
                }
                __syncthreads();

#pragma unroll 5
                for (int d = 0; d < 100; d++) {
                    float w0 = Wst[d][j], w1 = Wst[d][j + 32];
#pragma unroll
                    for (int r = 0; r < 4; r++) {
                        float e = Es[iy + r * 8][d];
                        a[r][0] += e * w0;
                        a[r][1] += e * w1;
                    }
                }
            }
#pragma unroll
            for (int r = 0; r < 4; r++) {
                int cc = r0 + iy + r * 8;
                if (cc < N_HW) {
                    store_tl(V_POI + cc, n0 + j,      a[r][0]);
                    store_tl(V_POI + cc, n0 + j + 32, a[r][1]);
                }
            }
        }
    } else {
        // ---------------- prep branch (coalesced via smem staging) --------
        int* obuf = reinterpret_cast<int*>(sbuf);       // [256][24]
        const int pid = (y - (YB_POI + YB_HW)) * 17 + blockIdx.x;   // 0..271
        const int s0  = pid * 256;
        if (s0 >= B) return;
        const int nv = min(256, B - s0);

        if (tid < nv) {
            const int s = s0 + tid;
            const int* xp = x + s * (L_WIN * 3);
            int* op = obuf + tid * 24;
#pragma unroll
            for (int l = 0; l < L_WIN; l++) {
                int p = __ldg(xp + 3 * l + 0);
                int h = __ldg(xp + 3 * l + 1);
                int w = __ldg(xp + 3 * l + 2);
                op[l]      = p * (TCOLS * 2);
                op[10 + l] = (h * V_WD + w) * (TCOLS * 2);
            }
            int e = min(max(lens[s], 1), L_WIN);
            op[20] = e;
            op[21] = __float_as_int(1.0f / (float)e);
            op[22] = 0;
            op[23] = 0;
        }
        __syncthreads();

        const int total = nv * 24;
        int* dst = g_off + (size_t)s0 * 24;
        for (int i = tid; i < total; i += 256)
            dst[i] = obuf[i];
    }
}

// ---------------------------------------------------------------------------
// Main gather: grid (4 tiles x 74 chunks) = 296 blocks (2/SM), 768 threads.
// Block loads its 86KB hw tile slice into SMEM once; poi rows stream from L2.
// Warp per sample: lane owns 8 cols (16B). fp16 adds <=2 deep, then fp32.
// (unchanged from R10/R11 — measured 133us at its L1 roofline)
// ---------------------------------------------------------------------------
__global__ void __launch_bounds__(BTHREADS, 2)
cbow_gather_kernel(const float* __restrict__ b_poi,
                   const float* __restrict__ b_hour,
                   float* __restrict__ out,
                   int B) {
    extern __shared__ __align__(16) char s_hw[];   // 86016 B hw tile slice

    const int ti = blockIdx.x;                     // column tile 0..3

    {   // cooperative slice load: 5376 uint4
        const uint4* src = reinterpret_cast<const uint4*>(
            reinterpret_cast<const char*>(g_hw_t) + (size_t)ti * HW_SLICE_BYTES);
        uint4* dst = reinterpret_cast<uint4*>(s_hw);
        for (int i = threadIdx.x; i < HW_SLICE_BYTES / 16; i += BTHREADS)
            dst[i] = src[i];
    }
    __syncthreads();

    const int w    = threadIdx.x >> 5;             // warp 0..23
    const int lane = threadIdx.x & 31;
    const int gw   = blockIdx.y * (BTHREADS / 32) + w;   // 0..1775
    const int nwarps = GY * (BTHREADS / 32);             // 1776

    const char* poi_base = reinterpret_cast<const char*>(g_poi_t)
                         + (size_t)ti * (V_POI * TCOLS * 2) + lane * 16;
    const char* hw_base  = s_hw + lane * 16;

    const int n0 = ti * TCOLS + lane * 8;          // 8 output cols per lane

    // fixed per-lane output mapping (boundary 1000 is 8-aligned: no straddle)
    const float* bias;
    float* dstbase; int stride;
    if (n0 < V_POI) {
        bias = b_poi + n0;
        dstbase = out + n0;                     stride = V_POI;
    } else {
        bias = b_hour + (n0 - V_POI);
        dstbase = out + (size_t)B * V_POI + (n0 - V_POI); stride = V_HOUR;
    }

    for (int s = gw; s < B; s += nwarps) {
        const int* op = g_off + s * 24;
        int v = (lane < 22) ? op[lane] : 0;
        const int   e   = __shfl_sync(0xffffffffu, v, 20);
        const float inv = __int_as_float(__shfl_sync(0xffffffffu, v, 21));

        float acc[8];
#pragma unroll
        for (int i = 0; i < 8; i++) acc[i] = 0.f;

        int t = 0;
#pragma unroll 2
        for (; t + 2 <= e; t += 2) {
            int po0 = __shfl_sync(0xffffffffu, v, t);
            int po1 = __shfl_sync(0xffffffffu, v, t + 1);
            int ho0 = __shfl_sync(0xffffffffu, v, 10 + t);
            int ho1 = __shfl_sync(0xffffffffu, v, 10 + t + 1);
            uint4 P0 = *reinterpret_cast<const uint4*>(poi_base + po0);
            uint4 P1 = *reinterpret_cast<const uint4*>(poi_base + po1);
            uint4 H0 = *reinterpret_cast<const uint4*>(hw_base + ho0);
            uint4 H1 = *reinterpret_cast<const uint4*>(hw_base + ho1);
            const unsigned* p0 = &P0.x; const unsigned* p1 = &P1.x;
            const unsigned* h0 = &H0.x; const unsigned* h1 = &H1.x;
#pragma unroll
            for (int i = 0; i < 4; i++) {
                __half2 a = __hadd2(*reinterpret_cast<const __half2*>(&p0[i]),
                                    *reinterpret_cast<const __half2*>(&h0[i]));
                __half2 b = __hadd2(*reinterpret_cast<const __half2*>(&p1[i]),
                                    *reinterpret_cast<const __half2*>(&h1[i]));
                float2 f = __half22float2(__hadd2(a, b));
                acc[2 * i]     += f.x;
                acc[2 * i + 1] += f.y;
            }
        }
        if (t < e) {                               // odd tail position
            int po = __shfl_sync(0xffffffffu, v, t);
            int ho = __shfl_sync(0xffffffffu, v, 10 + t);
            uint4 P = *reinterpret_cast<const uint4*>(poi_base + po);
            uint4 H = *reinterpret_cast<const uint4*>(hw_base + ho);
            const unsigned* p = &P.x; const unsigned* h = &H.x;
#pragma unroll
            for (int i = 0; i < 4; i++) {
                __half2 q = __hadd2(*reinterpret_cast<const __half2*>(&p[i]),
                                    *reinterpret_cast<const __half2*>(&h[i]));
                float2 f = __half22float2(q);
                acc[2 * i]     += f.x;
                acc[2 * i + 1] += f.y;
            }
        }

        float4 bv0 = *reinterpret_cast<const float4*>(bias);
        float4 bv1 = *reinterpret_cast<const float4*>(bias + 4);
        float4 o0, o1;
        o0.x = acc[0] * inv + bv0.x; o0.y = acc[1] * inv + bv0.y;
        o0.z = acc[2] * inv + bv0.z; o0.w = acc[3] * inv + bv0.w;
        o1.x = acc[4] * inv + bv1.x; o1.y = acc[5] * inv + bv1.y;
        o1.z = acc[6] * inv + bv1.z; o1.w = acc[7] * inv + bv1.w;
        float* dp = dstbase + (size_t)s * stride;
        *reinterpret_cast<float4*>(dp)     = o0;
        *reinterpret_cast<float4*>(dp + 4) = o1;
    }
}

// ---------------------------------------------------------------------------
// Weekday head: 8 threads per sample over the compact fp32 TLwd table.
// ---------------------------------------------------------------------------
__global__ void wd_kernel(const int* __restrict__ x,
                          const int* __restrict__ lens,
                          const float* __restrict__ b_wd,
                          float* __restrict__ out,
                          int B) {
    const int g = blockIdx.x * 32 + (threadIdx.x >> 3);
    const int k = threadIdx.x & 7;
    if (g >= B) return;

    int e = min(max(lens[g], 1), L_WIN);
    const int* xp = x + g * (L_WIN * 3);

    float acc = 0.f;
    for (int t = 0; t < e; t++) {
        int p = xp[t * 3 + 0];
        int h = xp[t * 3 + 1];
        int w = xp[t * 3 + 2];
        acc += g_TLwd[p * 8 + k];
        acc += g_TLwd[(V_POI + h * V_WD + w) * 8 + k];
    }
    if (k < V_WD)
        out[(size_t)B * (V_POI + V_HOUR) + (size_t)g * V_WD + k] =
            acc / (float)e + b_wd[k];
}

// ---------------------------------------------------------------------------
// Launch
// ---------------------------------------------------------------------------
extern "C" void kernel_launch(void* const* d_in, const int* in_sizes, int n_in,
                              void* d_out, int out_size) {
    const int*   x        = (const int*)  d_in[0];
    const int*   lens     = (const int*)  d_in[1];
    const float* emb_poi  = (const float*)d_in[2];
    const float* emb_hour = (const float*)d_in[3];
    const float* emb_wd   = (const float*)d_in[4];
    const float* W_poi    = (const float*)d_in[5];
    const float* b_poi    = (const float*)d_in[6];
    const float* W_hour   = (const float*)d_in[7];
    const float* b_hour   = (const float*)d_in[8];
    const float* W_wd     = (const float*)d_in[9];
    const float* b_wd     = (const float*)d_in[10];

    const int B = in_sizes[0] / (L_WIN * 3);

    cudaFuncSetAttribute(cbow_gather_kernel,
                         cudaFuncAttributeMaxDynamicSharedMemorySize,
                         HW_SLICE_BYTES);

    // One wide setup launch: builds + prep, all independent.
    setup_kernel<<<dim3(17, Y_TOTAL), dim3(32, 8)>>>(
        x, lens, emb_poi, emb_hour, emb_wd, W_poi, W_hour, W_wd, B);

    cbow_gather_kernel<<<dim3(NTILES, GY), BTHREADS, HW_SLICE_BYTES>>>(
        b_poi, b_hour, (float*)d_out, B);
    wd_kernel<<<(B + 31) / 32, 256>>>(x, lens, b_wd, (float*)d_out, B);
}

// round 15
// speedup vs baseline: 1.7480x; 1.1478x over previous
#include <cuda_runtime.h>
#include <cuda_fp16.h>

// Problem constants (fixed by the dataset)
#define L_WIN   10
#define D_EMB   100
#define V_POI   1000
#define V_HOUR  24
#define V_WD    7
#define N_HW    (V_HOUR * V_WD)           // 168 hour*weekday combo rows
#define NROWS   (V_POI + N_HW)            // 1168 token rows (for wd table)
#define NTILES  4                         // 4 column tiles x 256 cols = 1024
#define TCOLS   256
#define GY      74                        // gather grid.y: 4*74=296 blocks
#define BTHREADS 768                      // 24 warps
#define META    12                        // ints per sample in g_off

// Column-tiled poi token-logit table (fp16): [tile][1000 rows][256 cols].
__device__ __align__(128) __half g_poi_t[NTILES * V_POI * TCOLS];   // 2.05 MB
// Column-tiled hour*weekday combo table (fp16): [tile][168 rows][256 cols].
__device__ __align__(128) __half g_hw_t[NTILES * N_HW * TCOLS];     // 344 KB
// Compact weekday-logit table (fp32): cols [0,7) weekday logits, col 7 pad.
__device__ __align__(128) float g_TLwd[NROWS * 8];                  // 37 KB
// Per-sample meta (stride META ints):
// [0..9] = (poi_row<<8)|hw_idx packed, [10]=e, [11]=1/e bits.
__device__ int g_off[65536 * META];                                 // 3.1 MB

#define HW_SLICE_BYTES (N_HW * TCOLS * 2)   // 86016

// setup grid.y split
#define YB_POI  32     // poi build: 32 blocks of 32 rows  (covers 1024>=1000)
#define YB_HW   6      // hw build:  6 blocks of 32 combos (covers 192>=168)
#define YB_PREP 16     // prep: 16*17=272 blocks of 256 samples
#define Y_TOTAL (YB_POI + YB_HW + YB_PREP)   // 54

#define WSTRIDE 108    // smem word stride: conflict-free LDS.128 (108%32=12)

// ---------------------------------------------------------------------------
__device__ __forceinline__ void store_tl(int r, int n, float v) {
    if (n < 1024) {
        int tile = n >> 8, c = n & 255;
        if (r < V_POI)
            g_poi_t[(tile * V_POI + r) * TCOLS + c] = __float2half_rn(v);
        else
            g_hw_t[(tile * N_HW + (r - V_POI)) * TCOLS + c] = __float2half_rn(v);
    } else if (n < 1032) {
        g_TLwd[r * 8 + (n - 1024)] = v;
    }
}

// float4 fetch of W(n)[so+d .. so+d+3]; zero outside valid cols.
__device__ __forceinline__ float4 wload4(const float* __restrict__ W_poi,
                                         const float* __restrict__ W_hour,
                                         const float* __restrict__ W_wd,
                                         int n, int so, int d) {
    if (n < V_POI)          return *reinterpret_cast<const float4*>(W_poi  + n * 300 + so + d);
    if (n < V_POI + V_HOUR) return *reinterpret_cast<const float4*>(W_hour + (n - V_POI) * 300 + so + d);
    if (n < 1031) {
        return *reinterpret_cast<const float4*>(W_wd + (n - 1024) * 300 + so + d);
    }
    return make_float4(0.f, 0.f, 0.f, 0.f);
}

// ---------------------------------------------------------------------------
// Fused setup kernel: grid (17, 54), 256 threads (32x8).
//   y in [0,32)  : poi build tile (32 rows x 64 cols, 4x2 per thread)
//   y in [32,38) : hw  build tile (32 combos x 64 cols, 2 K-segments)
//   y in [38,54) : prep blocks    (272 blocks cover 65536 samples)
// Build smem: Wst[64][108] (27648B) + Es[32][108] (13824B) = 41472B.
// All smem traffic is float4 (LDS.128), Wst conflict-free, Es broadcast.
// ---------------------------------------------------------------------------
__global__ void __launch_bounds__(256)
setup_kernel(const int* __restrict__ x,
             const int* __restrict__ lens,
             const float* __restrict__ emb_poi,
             const float* __restrict__ emb_hour,
             const float* __restrict__ emb_wd,
             const float* __restrict__ W_poi,
             const float* __restrict__ W_hour,
             const float* __restrict__ W_wd,
             int B) {
    __shared__ __align__(16) char sbuf[41472];

    const int y   = blockIdx.y;
    const int tid = threadIdx.y * 32 + threadIdx.x;

    if (y < YB_POI + YB_HW) {
        // ---------------- build branch: 32 rows x 64 cols, 4x2/thread -----
        float (*Wst)[WSTRIDE] = reinterpret_cast<float (*)[WSTRIDE]>(sbuf);            // [64][108]
        float (*Es)[WSTRIDE]  = reinterpret_cast<float (*)[WSTRIDE]>(sbuf + 27648);    // [32][108]

        const int n0 = blockIdx.x * 64;
        const int j  = threadIdx.x;
        const int iy = threadIdx.y;        // rows iy, iy+8, iy+16, iy+24

        float a[4][2];
#pragma unroll
        for (int r = 0; r < 4; r++) { a[r][0] = 0.f; a[r][1] = 0.f; }

        if (y < YB_POI) {
            // ---- poi rows, K=100 ----
            const int r0 = y * 32;
            // W fill: 64 cols x 25 float4 (transposed: Wst[c][d])
            for (int idx = tid; idx < 64 * 25; idx += 256) {
                int c = idx / 25, f = idx - c * 25, d = f * 4;
                float4 v = wload4(W_poi, W_hour, W_wd, n0 + c, 0, d);
                *reinterpret_cast<float4*>(&Wst[c][d]) = v;
            }
            // E fill: 32 rows x 25 float4
            for (int idx = tid; idx < 32 * 25; idx += 256) {
                int i = idx / 25, f = idx - i * 25, d = f * 4;
                int r = r0 + i;
                float4 v = (r < V_POI)
                    ? *reinterpret_cast<const float4*>(emb_poi + r * D_EMB + d)
                    : make_float4(0.f, 0.f, 0.f, 0.f);
                *reinterpret_cast<float4*>(&Es[i][d]) = v;
            }
            __syncthreads();

#pragma unroll 5
            for (int d = 0; d < 100; d += 4) {
                float4 w0 = *reinterpret_cast<const float4*>(&Wst[j][d]);
                float4 w1 = *reinterpret_cast<const float4*>(&Wst[j + 32][d]);
#pragma unroll
                for (int r = 0; r < 4; r++) {
                    float4 e = *reinterpret_cast<const float4*>(&Es[iy + r * 8][d]);
                    a[r][0] += e.x * w0.x + e.y * w0.y + e.z * w0.z + e.w * w0.w;
                    a[r][1] += e.x * w1.x + e.y * w1.y + e.z * w1.z + e.w * w1.w;
                }
            }
#pragma unroll
            for (int r = 0; r < 4; r++) {
                int row = r0 + iy + r * 8;
                if (row < V_POI) {
                    store_tl(row, n0 + j,      a[r][0]);
                    store_tl(row, n0 + j + 32, a[r][1]);
                }
            }
        } else {
            // ---- hw combo rows, K=200 in two 100-passes ----
            const int r0 = (y - YB_POI) * 32;
            for (int seg = 0; seg < 2; seg++) {
                const int so = 100 + seg * 100;
                if (seg) __syncthreads();
                for (int idx = tid; idx < 64 * 25; idx += 256) {
                    int c = idx / 25, f = idx - c * 25, d = f * 4;
                    float4 v = wload4(W_poi, W_hour, W_wd, n0 + c, so, d);
                    *reinterpret_cast<float4*>(&Wst[c][d]) = v;
                }
                for (int idx = tid; idx < 32 * 25; idx += 256) {
                    int i = idx / 25, f = idx - i * 25, d = f * 4;
                    int cc = r0 + i;
                    float4 v = make_float4(0.f, 0.f, 0.f, 0.f);
                    if (cc < N_HW) {
                        int h = cc / V_WD, w = cc - h * V_WD;
                        v = (seg == 0)
                            ? *reinterpret_cast<const float4*>(emb_hour + h * D_EMB + d)
                            : *reinterpret_cast<const float4*>(emb_wd  + w * D_EMB + d);
                    }
                    *reinterpret_cast<float4*>(&Es[i][d]) = v;
                }
                __syncthreads();

#pragma unroll 5
                for (int d = 0; d < 100; d += 4) {
                    float4 w0 = *reinterpret_cast<const float4*>(&Wst[j][d]);
                    float4 w1 = *reinterpret_cast<const float4*>(&Wst[j + 32][d]);
#pragma unroll
                    for (int r = 0; r < 4; r++) {
                        float4 e = *reinterpret_cast<const float4*>(&Es[iy + r * 8][d]);
                        a[r][0] += e.x * w0.x + e.y * w0.y + e.z * w0.z + e.w * w0.w;
                        a[r][1] += e.x * w1.x + e.y * w1.y + e.z * w1.z + e.w * w1.w;
                    }
                }
            }
#pragma unroll
            for (int r = 0; r < 4; r++) {
                int cc = r0 + iy + r * 8;
                if (cc < N_HW) {
                    store_tl(V_POI + cc, n0 + j,      a[r][0]);
                    store_tl(V_POI + cc, n0 + j + 32, a[r][1]);
                }
            }
        }
    } else {
        // ---------------- prep branch (coalesced via smem staging) --------
        int* obuf = reinterpret_cast<int*>(sbuf);       // [256][META]
        const int pid = (y - (YB_POI + YB_HW)) * 17 + blockIdx.x;   // 0..271
        const int s0  = pid * 256;
        if (s0 >= B) return;
        const int nv = min(256, B - s0);

        if (tid < nv) {
            const int s = s0 + tid;
            const int* xp = x + s * (L_WIN * 3);
            int* op = obuf + tid * META;
#pragma unroll
            for (int l = 0; l < L_WIN; l++) {
                int p = __ldg(xp + 3 * l + 0);
                int h = __ldg(xp + 3 * l + 1);
                int w = __ldg(xp + 3 * l + 2);
                op[l] = (p << 8) | (h * V_WD + w);      // packed row pair
            }
            int e = min(max(lens[s], 1), L_WIN);
            op[10] = e;
            op[11] = __float_as_int(1.0f / (float)e);
        }
        __syncthreads();

        const int total = nv * META;
        int* dst = g_off + (size_t)s0 * META;
        for (int i = tid; i < total; i += 256)
            dst[i] = obuf[i];
    }
}

// ---------------------------------------------------------------------------
// Main gather: grid (4 tiles x 74 chunks) = 296 blocks (2/SM), 768 threads.
// Block loads its 86KB hw tile slice into SMEM once; poi rows stream from L2.
// Warp per sample: lane owns 8 cols (16B). Packed meta: 1 SHFL per row.
// Epilogue: each block computes the weekday head for its 222-sample slice.
// ---------------------------------------------------------------------------
__global__ void __launch_bounds__(BTHREADS, 2)
cbow_gather_kernel(const float* __restrict__ b_poi,
                   const float* __restrict__ b_hour,
                   const float* __restrict__ b_wd,
                   float* __restrict__ out,
                   int B) {
    extern __shared__ __align__(16) char s_hw[];   // 86016 B hw tile slice

    const int ti = blockIdx.x;                     // column tile 0..3

    {   // cooperative slice load: 5376 uint4
        const uint4* src = reinterpret_cast<const uint4*>(
            reinterpret_cast<const char*>(g_hw_t) + (size_t)ti * HW_SLICE_BYTES);
        uint4* dst = reinterpret_cast<uint4*>(s_hw);
        for (int i = threadIdx.x; i < HW_SLICE_BYTES / 16; i += BTHREADS)
            dst[i] = src[i];
    }
    __syncthreads();

    const int w    = threadIdx.x >> 5;             // warp 0..23
    const int lane = threadIdx.x & 31;
    const int gw   = blockIdx.y * (BTHREADS / 32) + w;   // 0..1775
    const int nwarps = GY * (BTHREADS / 32);             // 1776

    const char* poi_base = reinterpret_cast<const char*>(g_poi_t)
                         + (size_t)ti * (V_POI * TCOLS * 2) + lane * 16;
    const char* hw_base  = s_hw + lane * 16;

    const int n0 = ti * TCOLS + lane * 8;          // 8 output cols per lane

    // fixed per-lane output mapping (boundary 1000 is 8-aligned: no straddle)
    const float* bias;
    float* dstbase; int stride;
    if (n0 < V_POI) {
        bias = b_poi + n0;
        dstbase = out + n0;                     stride = V_POI;
    } else {
        bias = b_hour + (n0 - V_POI);
        dstbase = out + (size_t)B * V_POI + (n0 - V_POI); stride = V_HOUR;
    }

    for (int s = gw; s < B; s += nwarps) {
        const int* op = g_off + s * META;
        int v = (lane < META) ? op[lane] : 0;
        const int   e   = __shfl_sync(0xffffffffu, v, 10);
        const float inv = __int_as_float(__shfl_sync(0xffffffffu, v, 11));

        float acc[8];
#pragma unroll
        for (int i = 0; i < 8; i++) acc[i] = 0.f;

        int t = 0;
#pragma unroll 2
        for (; t + 2 <= e; t += 2) {
            int v0 = __shfl_sync(0xffffffffu, v, t);
            int v1 = __shfl_sync(0xffffffffu, v, t + 1);
            int po0 = (v0 >> 8) << 9, ho0 = (v0 & 255) << 9;
            int po1 = (v1 >> 8) << 9, ho1 = (v1 & 255) << 9;
            uint4 P0 = *reinterpret_cast<const uint4*>(poi_base + po0);
            uint4 P1 = *reinterpret_cast<const uint4*>(poi_base + po1);
            uint4 H0 = *reinterpret_cast<const uint4*>(hw_base + ho0);
            uint4 H1 = *reinterpret_cast<const uint4*>(hw_base + ho1);
            const unsigned* p0 = &P0.x; const unsigned* p1 = &P1.x;
            const unsigned* h0 = &H0.x; const unsigned* h1 = &H1.x;
#pragma unroll
            for (int i = 0; i < 4; i++) {
                __half2 a = __hadd2(*reinterpret_cast<const __half2*>(&p0[i]),
                                    *reinterpret_cast<const __half2*>(&h0[i]));
                __half2 b = __hadd2(*reinterpret_cast<const __half2*>(&p1[i]),
                                    *reinterpret_cast<const __half2*>(&h1[i]));
                float2 f = __half22float2(__hadd2(a, b));
                acc[2 * i]     += f.x;
                acc[2 * i + 1] += f.y;
            }
        }
        if (t < e) {                               // odd tail position
            int v0 = __shfl_sync(0xffffffffu, v, t);
            int po = (v0 >> 8) << 9, ho = (v0 & 255) << 9;
            uint4 P = *reinterpret_cast<const uint4*>(poi_base + po);
            uint4 H = *reinterpret_cast<const uint4*>(hw_base + ho);
            const unsigned* p = &P.x; const unsigned* h = &H.x;
#pragma unroll
            for (int i = 0; i < 4; i++) {
                __half2 q = __hadd2(*reinterpret_cast<const __half2*>(&p[i]),
                                    *reinterpret_cast<const __half2*>(&h[i]));
                float2 f = __half22float2(q);
                acc[2 * i]     += f.x;
                acc[2 * i + 1] += f.y;
            }
        }

        float4 bv0 = *reinterpret_cast<const float4*>(bias);
        float4 bv1 = *reinterpret_cast<const float4*>(bias + 4);
        float4 o0, o1;
        o0.x = acc[0] * inv + bv0.x; o0.y = acc[1] * inv + bv0.y;
        o0.z = acc[2] * inv + bv0.z; o0.w = acc[3] * inv + bv0.w;
        o1.x = acc[4] * inv + bv1.x; o1.y = acc[5] * inv + bv1.y;
        o1.z = acc[6] * inv + bv1.z; o1.w = acc[7] * inv + bv1.w;
        float* dp = dstbase + (size_t)s * stride;
        *reinterpret_cast<float4*>(dp)     = o0;
        *reinterpret_cast<float4*>(dp + 4) = o1;
    }

    // -------- weekday epilogue: this block's 222-sample slice --------------
    {
        const int bid   = ti * GY + blockIdx.y;        // 0..295
        const int per   = (B + NTILES * GY - 1) / (NTILES * GY);   // 222
        const int sbeg  = bid * per;
        const int send  = min(sbeg + per, B);
        const int cnt   = (send - sbeg) * 8;
        float* owd = out + (size_t)B * (V_POI + V_HOUR);

        for (int i = threadIdx.x; i < cnt; i += BTHREADS) {
            const int s = sbeg + (i >> 3);
            const int k = i & 7;
            const int* op = g_off + s * META;
            const int   e   = op[10];
            const float inv = __int_as_float(op[11]);
            float acc = 0.f;
            for (int t = 0; t < e; t++) {
                int v = op[t];
                acc += g_TLwd[(v >> 8) * 8 + k];
                acc += g_TLwd[(V_POI + (v & 255)) * 8 + k];
            }
            if (k < V_WD)
                owd[(size_t)s * V_WD + k] = acc * inv + b_wd[k];
        }
    }
}

// ---------------------------------------------------------------------------
// Launch
// ---------------------------------------------------------------------------
extern "C" void kernel_launch(void* const* d_in, const int* in_sizes, int n_in,
                              void* d_out, int out_size) {
    const int*   x        = (const int*)  d_in[0];
    const int*   lens     = (const int*)  d_in[1];
    const float* emb_poi  = (const float*)d_in[2];
    const float* emb_hour = (const float*)d_in[3];
    const float* emb_wd   = (const float*)d_in[4];
    const float* W_poi    = (const float*)d_in[5];
    const float* b_poi    = (const float*)d_in[6];
    const float* W_hour   = (const float*)d_in[7];
    const float* b_hour   = (const float*)d_in[8];
    const float* W_wd     = (const float*)d_in[9];
    const float* b_wd     = (const float*)d_in[10];

    const int B = in_sizes[0] / (L_WIN * 3);

    cudaFuncSetAttribute(cbow_gather_kernel,
                         cudaFuncAttributeMaxDynamicSharedMemorySize,
                         HW_SLICE_BYTES);

    // One wide setup launch: builds + prep, all independent.
    setup_kernel<<<dim3(17, Y_TOTAL), dim3(32, 8)>>>(
        x, lens, emb_poi, emb_hour, emb_wd, W_poi, W_hour, W_wd, B);

    cbow_gather_kernel<<<dim3(NTILES, GY), BTHREADS, HW_SLICE_BYTES>>>(
        b_poi, b_hour, b_wd, (float*)d_out, B);
}